// round 13
// baseline (speedup 1.0000x reference)
#include <cuda_runtime.h>

#define BB 8
#define NN 4096
#define DD 64
#define SP 1024   // NPOINT
#define KS 32     // NSAMPLE
#define NC 8      // centers per MLP block
#define XS 36     // activation row stride (floats); 16B-aligned rows
#define FULLM 0xffffffffu

__device__ int g_gidx[BB * SP * KS];
__device__ float g_w0t[67 * 64];                     // [c][o] scalar (zprep fallback fill)
__device__ unsigned long long g_w0d[67 * 64];        // [c][o] duplicated-pair weights
__device__ unsigned long long g_w1d[64 * 64];        // [c][o] duplicated-pair weights
__device__ unsigned long long g_w2d[64 * 128];       // [c][o] duplicated-pair weights
__device__ float g_scbi[512];                        // sc[256] | bi[256]
__device__ float g_dw[3 * 64];                       // sc0[o]*W0[o][c], c<3
__device__ float g_z[BB * NN * 64];                  // precomputed layer0 (abs coords)
__device__ float4 g_xyz4[BB * NN];                   // xyz as float4 (w=0)

// ---------------- f32x2 packed helpers (per-half .rn == scalar .rn) --------
__device__ __forceinline__ unsigned long long packf2(float a, float b) {
    unsigned long long r;
    unsigned ua = __float_as_uint(a), ub = __float_as_uint(b);
    asm("mov.b64 %0, {%1, %2};" : "=l"(r) : "r"(ua), "r"(ub));
    return r;
}
__device__ __forceinline__ void unpackf2(unsigned long long v, float& a, float& b) {
    unsigned ua, ub;
    asm("mov.b64 {%0, %1}, %2;" : "=r"(ua), "=r"(ub) : "l"(v));
    a = __uint_as_float(ua); b = __uint_as_float(ub);
}
__device__ __forceinline__ unsigned long long addf2(unsigned long long a, unsigned long long b) {
    unsigned long long r;
    asm("add.rn.f32x2 %0, %1, %2;" : "=l"(r) : "l"(a), "l"(b));
    return r;
}
__device__ __forceinline__ unsigned long long mulf2(unsigned long long a, unsigned long long b) {
    unsigned long long r;
    asm("mul.rn.f32x2 %0, %1, %2;" : "=l"(r) : "l"(a), "l"(b));
    return r;
}
__device__ __forceinline__ void fmaf2(unsigned long long& acc, unsigned long long a,
                                      unsigned long long b) {
    asm("fma.rn.f32x2 %0, %1, %2, %0;" : "+l"(acc) : "l"(a), "l"(b));
}

// ---------------------------------------------------------------------------
// xyz -> float4 shadow buffer.
// ---------------------------------------------------------------------------
__global__ __launch_bounds__(256) void xyz4_kernel(const float* __restrict__ xyz) {
    int i = blockIdx.x * 256 + threadIdx.x;
    if (i < BB * NN)
        g_xyz4[i] = make_float4(xyz[3 * i], xyz[3 * i + 1], xyz[3 * i + 2], 0.f);
}

// ---------------------------------------------------------------------------
// FPS — R10 verbatim (best measured: 312.6us). One block/batch, 512 threads
// x 8 points (4 f32x2 pairs), IN-LOOP argmax interleaved with distance math,
// REDUX.SYNC reductions, one barrier + parity partials, float4 centroid LDG.
// Distances (dx^2+dy^2)+dz^2 all .rn == reference; first-index tie-break.
// ---------------------------------------------------------------------------
__global__ __launch_bounds__(512) void fps_kernel(float* __restrict__ newxyz) {
    const int b = blockIdx.x;
    const int tid = threadIdx.x;
    const int lane = tid & 31;
    const int w = tid >> 5;                 // 16 warps
    __shared__ unsigned long long part[2][16];

    const float4* xb4 = g_xyz4 + (size_t)b * NN;
    unsigned long long pxp[4], pyp[4], pzp[4];
    float dist[8];
#pragma unroll
    for (int jp = 0; jp < 4; jp++) {
        float4 f0 = __ldg(xb4 + tid + (2 * jp) * 512);
        float4 f1 = __ldg(xb4 + tid + (2 * jp + 1) * 512);
        pxp[jp] = packf2(f0.x, f1.x);
        pyp[jp] = packf2(f0.y, f1.y);
        pzp[jp] = packf2(f0.z, f1.z);
        dist[2 * jp] = 1e10f;
        dist[2 * jp + 1] = 1e10f;
    }

    int far = 0;
    for (int it = 0; it < SP; it++) {
        const int p = it & 1;
        float4 cen = __ldg(xb4 + far);      // 1 LDG.128 on the critical path
        if (tid == 0) {
            size_t o = ((size_t)b * SP + it) * 3;
            newxyz[o] = cen.x; newxyz[o + 1] = cen.y; newxyz[o + 2] = cen.z;
        }
        unsigned long long ncx = packf2(-cen.x, -cen.x);
        unsigned long long ncy = packf2(-cen.y, -cen.y);
        unsigned long long ncz = packf2(-cen.z, -cen.z);

        float bd = -1.0f;
        int bj = 0;
#pragma unroll
        for (int jp = 0; jp < 4; jp++) {
            unsigned long long dx = addf2(pxp[jp], ncx);   // a-b == a+(-b) exactly
            unsigned long long dy = addf2(pyp[jp], ncy);
            unsigned long long dz = addf2(pzp[jp], ncz);
            unsigned long long s = addf2(mulf2(dx, dx), mulf2(dy, dy));
            s = addf2(s, mulf2(dz, dz));
            float d0, d1;
            unpackf2(s, d0, d1);
            d0 = fminf(dist[2 * jp], d0);
            d1 = fminf(dist[2 * jp + 1], d1);
            dist[2 * jp] = d0;
            dist[2 * jp + 1] = d1;
            if (d0 > bd) { bd = d0; bj = 2 * jp; }       // strict > keeps earliest j
            if (d1 > bd) { bd = d1; bj = 2 * jp + 1; }
        }
        unsigned gidx = (unsigned)(tid + bj * 512);
        unsigned ub = __float_as_uint(bd);               // positive floats monotone as u32
        unsigned m = __reduce_max_sync(FULLM, ub);
        unsigned key = (ub == m) ? gidx : 0x7fffffffu;
        unsigned mi = __reduce_min_sync(FULLM, key);
        if (lane == 0) part[p][w] = ((unsigned long long)m << 32) | mi;
        __syncthreads();
        unsigned long long v = part[p][lane & 15];       // dup lanes harmless for max/min
        unsigned um = (unsigned)(v >> 32);
        unsigned ui = (unsigned)v;
        unsigned m2 = __reduce_max_sync(FULLM, um);
        unsigned key2 = (um == m2) ? ui : 0x7fffffffu;
        far = (int)__reduce_min_sync(FULLM, key2);
        // no second barrier: parity double-buffer
    }
}

// ---------------------------------------------------------------------------
// Ball query: one warp per center; 64 points per loop iteration via float4
// loads. First KS hits in ascending index order.
// ---------------------------------------------------------------------------
__global__ __launch_bounds__(128) void ballquery_kernel(const float* __restrict__ newxyz) {
    int gw = blockIdx.x * 4 + (threadIdx.x >> 5);
    int lane = threadIdx.x & 31;
    int b = gw >> 10;
    int s = gw & 1023;
    const float4* xb4 = g_xyz4 + (size_t)b * NN;
    size_t ci = (size_t)b * SP + s;
    float cx = newxyz[ci * 3], cy = newxyz[ci * 3 + 1], cz = newxyz[ci * 3 + 2];
    int* gp = g_gidx + ci * KS;
    const unsigned lm = (1u << lane) - 1u;

    int count = 0, first = -1;
    for (int base = 0; base < NN; base += 64) {
        int j0 = base + lane;
        int j1 = j0 + 32;
        float4 p0 = __ldg(xb4 + j0);
        float4 p1 = __ldg(xb4 + j1);
        float da = __fadd_rn(__fadd_rn(__fmul_rn(__fsub_rn(cx, p0.x), __fsub_rn(cx, p0.x)),
                                       __fmul_rn(__fsub_rn(cy, p0.y), __fsub_rn(cy, p0.y))),
                             __fmul_rn(__fsub_rn(cz, p0.z), __fsub_rn(cz, p0.z)));
        float db = __fadd_rn(__fadd_rn(__fmul_rn(__fsub_rn(cx, p1.x), __fsub_rn(cx, p1.x)),
                                       __fmul_rn(__fsub_rn(cy, p1.y), __fsub_rn(cy, p1.y))),
                             __fmul_rn(__fsub_rn(cz, p1.z), __fsub_rn(cz, p1.z)));
        bool va = !(da > 0.04f);
        bool vb = !(db > 0.04f);
        unsigned m0 = __ballot_sync(FULLM, va);
        unsigned m1 = __ballot_sync(FULLM, vb);
        if (first < 0) {
            if (m0) first = base + __ffs(m0) - 1;
            else if (m1) first = base + 32 + __ffs(m1) - 1;
        }
        int pos0 = count + __popc(m0 & lm);
        if (va && pos0 < KS) gp[pos0] = j0;
        int c0 = count + __popc(m0);
        int pos1 = c0 + __popc(m1 & lm);
        if (vb && pos1 < KS) gp[pos1] = j1;
        count = c0 + __popc(m1);
        if (count >= KS) break;
    }
    if (lane >= count) gp[lane] = first;
}

// ---------------------------------------------------------------------------
// Prep: fold BN into scale/bias; transpose weights to [c][o] with DUPLICATED
// pair packing (w,w) as u64 -- removes per-c mov.b64 packing from all MLP
// inner loops; g_dw for the center-delta trick.
// ---------------------------------------------------------------------------
__global__ void prep_kernel(
    const float* __restrict__ w0, const float* __restrict__ b0,
    const float* __restrict__ g0, const float* __restrict__ be0,
    const float* __restrict__ m0, const float* __restrict__ v0,
    const float* __restrict__ w1, const float* __restrict__ b1,
    const float* __restrict__ g1, const float* __restrict__ be1,
    const float* __restrict__ m1, const float* __restrict__ v1,
    const float* __restrict__ w2, const float* __restrict__ b2,
    const float* __restrict__ g2, const float* __restrict__ be2,
    const float* __restrict__ m2, const float* __restrict__ v2) {
    int t = threadIdx.x;  // 256
    {
        float g, bb, be, m, v;
        if (t < 64)       { int o = t;       g = g0[o]; bb = b0[o]; be = be0[o]; m = m0[o]; v = v0[o]; }
        else if (t < 128) { int o = t - 64;  g = g1[o]; bb = b1[o]; be = be1[o]; m = m1[o]; v = v1[o]; }
        else              { int o = t - 128; g = g2[o]; bb = b2[o]; be = be2[o]; m = m2[o]; v = v2[o]; }
        float sc = g * rsqrtf(v + 1e-5f);
        g_scbi[t] = sc;
        g_scbi[256 + t] = fmaf(sc, bb - m, be);
    }
    if (t < 192) {  // g_dw[c][o] = sc0[o] * w0[o][c], c<3 (sc recomputed, no bar)
        int c = t >> 6, o = t & 63;
        g_dw[t] = g0[o] * rsqrtf(v0[o] + 1e-5f) * w0[o * 67 + c];
    }
    for (int i = t; i < 64 * 67; i += 256) {
        int o = i / 67, c = i - o * 67;
        float wv = w0[i];
        g_w0t[c * 64 + o] = wv;
        g_w0d[c * 64 + o] = packf2(wv, wv);
    }
    for (int i = t; i < 64 * 64; i += 256) {
        int o = i >> 6, c = i & 63;
        float wv = w1[i];
        g_w1d[c * 64 + o] = packf2(wv, wv);
    }
    for (int i = t; i < 128 * 64; i += 256) {
        int o = i >> 6, c = i & 63;
        float wv = w2[i];
        g_w2d[c * 128 + o] = packf2(wv, wv);
    }
}

// ---------------------------------------------------------------------------
// Z precompute: Z[j][o] = sc0[o]*(W0 @ [xyz_j; pts_j])[o] + bi0[o]  (no relu).
// Uses duplicated-pair weights (1 LDG.128 = 2 packed weights, no movs).
// ---------------------------------------------------------------------------
__global__ __launch_bounds__(128) void zprep_kernel(const float* __restrict__ xyz,
                                                    const float* __restrict__ points) {
    __shared__ __align__(16) float sF[67 * XS];
    __shared__ __align__(16) float sB[32 * 64];   // [k][o] for coalesced STG
    int t = threadIdx.x;
    int lane = t & 31, kg = t >> 5;
    int b = blockIdx.x >> 7;
    int j0 = (blockIdx.x & 127) * 32;
    const size_t rowb = (size_t)b * NN + j0;

    if (t < 96) { int c = t / 32, k = t % 32; sF[c * XS + k] = xyz[(rowb + k) * 3 + c]; }
    for (int i = t; i < 32 * 64; i += 128) {
        int c = i & 63, k = i >> 6;
        sF[(3 + c) * XS + k] = points[(rowb + k) * DD + c];
    }
    __syncthreads();

    unsigned long long acc[2][4];
#pragma unroll
    for (int i = 0; i < 2; i++)
#pragma unroll
        for (int jp = 0; jp < 4; jp++) acc[i][jp] = 0ull;
    const float* xbase = sF + kg * 8;
#pragma unroll 4
    for (int c = 0; c < 67; c++) {
        ulonglong2 xv01 = *(const ulonglong2*)(xbase + c * XS);
        ulonglong2 xv23 = *(const ulonglong2*)(xbase + c * XS + 4);
        ulonglong2 wp = *(const ulonglong2*)(g_w0d + c * 64 + 2 * lane);
        fmaf2(acc[0][0], xv01.x, wp.x); fmaf2(acc[0][1], xv01.y, wp.x);
        fmaf2(acc[0][2], xv23.x, wp.x); fmaf2(acc[0][3], xv23.y, wp.x);
        fmaf2(acc[1][0], xv01.x, wp.y); fmaf2(acc[1][1], xv01.y, wp.y);
        fmaf2(acc[1][2], xv23.x, wp.y); fmaf2(acc[1][3], xv23.y, wp.y);
    }
    {
        int o = 2 * lane;
        float s0 = g_scbi[o], b0_ = g_scbi[256 + o];
        float s1 = g_scbi[o + 1], b1_ = g_scbi[256 + o + 1];
#pragma unroll
        for (int jp = 0; jp < 4; jp++) {
            float a0, a1, c0, c1;
            unpackf2(acc[0][jp], a0, a1);
            unpackf2(acc[1][jp], c0, c1);
            int k = kg * 8 + 2 * jp;
            *(float2*)(sB + k * 64 + o) = make_float2(fmaf(a0, s0, b0_), fmaf(c0, s1, b1_));
            *(float2*)(sB + (k + 1) * 64 + o) = make_float2(fmaf(a1, s0, b0_), fmaf(c1, s1, b1_));
        }
    }
    __syncthreads();
    for (int i = t; i < 32 * 64; i += 128) {
        int o = i & 63, k = i >> 6;
        g_z[(rowb + k) * 64 + o] = sB[k * 64 + o];
    }
}

// ---------------------------------------------------------------------------
// MLP layers l1/l2 with duplicated-pair weights (no per-c packing movs).
// Activations [c][k] stride XS; warp kg owns k kg*8..+7.
// ---------------------------------------------------------------------------
__device__ __forceinline__ void layer64(const float* __restrict__ X,
                                        const unsigned long long* __restrict__ Wd,
                                        float* __restrict__ Y,
                                        const float* __restrict__ scp,
                                        const float* __restrict__ bip,
                                        int kg, int lane) {
    unsigned long long acc[2][4];
#pragma unroll
    for (int i = 0; i < 2; i++)
#pragma unroll
        for (int jp = 0; jp < 4; jp++) acc[i][jp] = 0ull;
    const float* xbase = X + kg * 8;
#pragma unroll 4
    for (int c = 0; c < 64; c++) {
        ulonglong2 xv01 = *(const ulonglong2*)(xbase + c * XS);
        ulonglong2 xv23 = *(const ulonglong2*)(xbase + c * XS + 4);
        ulonglong2 wp = *(const ulonglong2*)(Wd + c * 64 + 2 * lane);
        fmaf2(acc[0][0], xv01.x, wp.x); fmaf2(acc[0][1], xv01.y, wp.x);
        fmaf2(acc[0][2], xv23.x, wp.x); fmaf2(acc[0][3], xv23.y, wp.x);
        fmaf2(acc[1][0], xv01.x, wp.y); fmaf2(acc[1][1], xv01.y, wp.y);
        fmaf2(acc[1][2], xv23.x, wp.y); fmaf2(acc[1][3], xv23.y, wp.y);
    }
#pragma unroll
    for (int i = 0; i < 2; i++) {
        int o = 2 * lane + i;
        float s = scp[o], bb = bip[o];
        float* yr = Y + o * XS + kg * 8;
#pragma unroll
        for (int jp = 0; jp < 4; jp++) {   // k-contiguous: STS.64 pairs
            float v0, v1;
            unpackf2(acc[i][jp], v0, v1);
            *(float2*)(yr + 2 * jp) = make_float2(fmaxf(fmaf(v0, s, bb), 0.f),
                                                  fmaxf(fmaf(v1, s, bb), 0.f));
        }
    }
}

__device__ __forceinline__ void layer128max(const float* __restrict__ X,
                                            const unsigned long long* __restrict__ Wd,
                                            float* __restrict__ spm,
                                            const float* __restrict__ scp,
                                            const float* __restrict__ bip,
                                            int kg, int lane) {
    unsigned long long acc[4][4];
#pragma unroll
    for (int i = 0; i < 4; i++)
#pragma unroll
        for (int jp = 0; jp < 4; jp++) acc[i][jp] = 0ull;
    const float* xbase = X + kg * 8;
#pragma unroll 2
    for (int c = 0; c < 64; c++) {
        ulonglong2 xv01 = *(const ulonglong2*)(xbase + c * XS);
        ulonglong2 xv23 = *(const ulonglong2*)(xbase + c * XS + 4);
        ulonglong2 wp01 = *(const ulonglong2*)(Wd + c * 128 + 4 * lane);
        ulonglong2 wp23 = *(const ulonglong2*)(Wd + c * 128 + 4 * lane + 2);
        fmaf2(acc[0][0], xv01.x, wp01.x); fmaf2(acc[0][1], xv01.y, wp01.x);
        fmaf2(acc[0][2], xv23.x, wp01.x); fmaf2(acc[0][3], xv23.y, wp01.x);
        fmaf2(acc[1][0], xv01.x, wp01.y); fmaf2(acc[1][1], xv01.y, wp01.y);
        fmaf2(acc[1][2], xv23.x, wp01.y); fmaf2(acc[1][3], xv23.y, wp01.y);
        fmaf2(acc[2][0], xv01.x, wp23.x); fmaf2(acc[2][1], xv01.y, wp23.x);
        fmaf2(acc[2][2], xv23.x, wp23.x); fmaf2(acc[2][3], xv23.y, wp23.x);
        fmaf2(acc[3][0], xv01.x, wp23.y); fmaf2(acc[3][1], xv01.y, wp23.y);
        fmaf2(acc[3][2], xv23.x, wp23.y); fmaf2(acc[3][3], xv23.y, wp23.y);
    }
#pragma unroll
    for (int i = 0; i < 4; i++) {
        int o = 4 * lane + i;
        float s = scp[o], bb = bip[o];
        float mx = 0.f;  // relu >= 0
#pragma unroll
        for (int jp = 0; jp < 4; jp++) {
            float v0, v1;
            unpackf2(acc[i][jp], v0, v1);
            mx = fmaxf(mx, fmaf(v0, s, bb));
            mx = fmaxf(mx, fmaf(v1, s, bb));
        }
        spm[kg * 128 + o] = mx;
    }
}

// ---------------------------------------------------------------------------
// MLP: gather pipelined one center ahead; sgid in registers + shfl; dvec
// per-thread from hoisted g_dw registers. 2 barriers per center.
// ---------------------------------------------------------------------------
__global__ __launch_bounds__(128) void mlp_kernel(const float* __restrict__ newxyz,
                                                  float* __restrict__ outp) {
    __shared__ __align__(16) float sA[64 * XS];
    __shared__ __align__(16) float sB[64 * XS];
    __shared__ float spm[512];

    int t = threadIdx.x;
    int lane = t & 31, kg = t >> 5;
    int b = blockIdx.x >> 7;
    int sbase = (blockIdx.x & 127) * NC;
    const float* sc = g_scbi;
    const float* bi = g_scbi + 256;
    const float* zb = g_z + (size_t)b * NN * 64;
    const int f4 = (t & 15) * 4;          // base channel for this thread
    const int kb = t >> 4;                // base k (0..7)

    const float4 dwx = *(const float4*)(g_dw + f4);
    const float4 dwy = *(const float4*)(g_dw + 64 + f4);
    const float4 dwz = *(const float4*)(g_dw + 128 + f4);

    size_t ci0 = (size_t)b * SP + sbase;

    int sgid_r = g_gidx[ci0 * KS + lane];
    float4 dv;
    {
        float cx = __ldg(newxyz + ci0 * 3);
        float cy = __ldg(newxyz + ci0 * 3 + 1);
        float cz = __ldg(newxyz + ci0 * 3 + 2);
        dv.x = -(dwx.x * cx + dwy.x * cy + dwz.x * cz);
        dv.y = -(dwx.y * cx + dwy.y * cy + dwz.y * cz);
        dv.z = -(dwx.z * cx + dwy.z * cy + dwz.z * cz);
        dv.w = -(dwx.w * cx + dwy.w * cy + dwz.w * cz);
    }
    float4 zr[4];
#pragma unroll
    for (int j = 0; j < 4; j++) {
        int row = __shfl_sync(FULLM, sgid_r, kb + 8 * j);
        zr[j] = *(const float4*)(zb + (size_t)row * 64 + f4);
    }

    for (int cc = 0; cc < NC; cc++) {
        size_t ci = ci0 + cc;
#pragma unroll
        for (int j = 0; j < 4; j++) {
            int k = kb + 8 * j;
            sA[(f4 + 0) * XS + k] = fmaxf(zr[j].x + dv.x, 0.f);
            sA[(f4 + 1) * XS + k] = fmaxf(zr[j].y + dv.y, 0.f);
            sA[(f4 + 2) * XS + k] = fmaxf(zr[j].z + dv.z, 0.f);
            sA[(f4 + 3) * XS + k] = fmaxf(zr[j].w + dv.w, 0.f);
        }
        if (cc + 1 < NC) {
            size_t cin = ci + 1;
            sgid_r = g_gidx[cin * KS + lane];
            float cx = __ldg(newxyz + cin * 3);
            float cy = __ldg(newxyz + cin * 3 + 1);
            float cz = __ldg(newxyz + cin * 3 + 2);
            dv.x = -(dwx.x * cx + dwy.x * cy + dwz.x * cz);
            dv.y = -(dwx.y * cx + dwy.y * cy + dwz.y * cz);
            dv.z = -(dwx.z * cx + dwy.z * cy + dwz.z * cz);
            dv.w = -(dwx.w * cx + dwy.w * cy + dwz.w * cz);
#pragma unroll
            for (int j = 0; j < 4; j++) {
                int row = __shfl_sync(FULLM, sgid_r, kb + 8 * j);
                zr[j] = *(const float4*)(zb + (size_t)row * 64 + f4);
            }
        }
        __syncthreads();

        layer64(sA, g_w1d, sB, sc + 64, bi + 64, kg, lane);
        __syncwarp();   // sB k-slices warp-local; order STS->LDS within warp
        layer128max(sB, g_w2d, spm, sc + 128, bi + 128, kg, lane);
        __syncthreads();

        float r = fmaxf(fmaxf(spm[t], spm[128 + t]), fmaxf(spm[256 + t], spm[384 + t]));
        outp[ci * 128 + t] = r;
    }
}

// ---------------------------------------------------------------------------
// Single-stream, serial (overlap measured as a loser in R6/R7).
// ---------------------------------------------------------------------------
extern "C" void kernel_launch(void* const* d_in, const int* in_sizes, int n_in,
                              void* d_out, int out_size) {
    const float* xyz = (const float*)d_in[0];
    const float* points = (const float*)d_in[1];
    const float* w0 = (const float*)d_in[2];
    const float* b0 = (const float*)d_in[3];
    const float* g0 = (const float*)d_in[4];
    const float* be0 = (const float*)d_in[5];
    const float* m0 = (const float*)d_in[6];
    const float* v0 = (const float*)d_in[7];
    const float* w1 = (const float*)d_in[8];
    const float* b1 = (const float*)d_in[9];
    const float* g1 = (const float*)d_in[10];
    const float* be1 = (const float*)d_in[11];
    const float* m1 = (const float*)d_in[12];
    const float* v1 = (const float*)d_in[13];
    const float* w2 = (const float*)d_in[14];
    const float* b2 = (const float*)d_in[15];
    const float* g2 = (const float*)d_in[16];
    const float* be2 = (const float*)d_in[17];
    const float* m2 = (const float*)d_in[18];
    const float* v2 = (const float*)d_in[19];

    float* out = (float*)d_out;
    float* newxyz = out;                          // [B, SP, 3]
    float* newpts = out + (size_t)BB * SP * 3;    // [B, SP, 128]

    xyz4_kernel<<<(BB * NN + 255) / 256, 256>>>(xyz);
    prep_kernel<<<1, 256>>>(w0, b0, g0, be0, m0, v0,
                            w1, b1, g1, be1, m1, v1,
                            w2, b2, g2, be2, m2, v2);
    zprep_kernel<<<BB * NN / 32, 128>>>(xyz, points);
    fps_kernel<<<BB, 512>>>(newxyz);
    ballquery_kernel<<<BB * SP / 4, 128>>>(newxyz);
    mlp_kernel<<<BB * SP / NC, 128>>>(newxyz, newpts);
}

// round 14
// speedup vs baseline: 1.3620x; 1.3620x over previous
#include <cuda_runtime.h>

#define BB 8
#define NN 4096
#define DD 64
#define SP 1024   // NPOINT
#define KS 32     // NSAMPLE
#define NC 8      // centers per MLP block
#define XS 36     // activation row stride (floats); 16B-aligned rows
#define FULLM 0xffffffffu

__device__ int g_gidx[BB * SP * KS];
__device__ float g_w0t[67 * 64];            // [c][o]
__device__ float g_w1t[64 * 64];            // [c][o]
__device__ float g_w2t[64 * 128];           // [c][o]
__device__ float g_scbi[512];               // sc[256] | bi[256]
__device__ float g_dw[3 * 64];              // sc0[o]*W0[o][c], c<3
__device__ float g_z[BB * NN * 64];         // precomputed layer0 (abs coords), 8MB
__device__ float4 g_xyz4[BB * NN];          // xyz as float4 (w=0), filled by zprep

// ---------------- f32x2 packed helpers (per-half .rn == scalar .rn) --------
__device__ __forceinline__ unsigned long long packf2(float a, float b) {
    unsigned long long r;
    unsigned ua = __float_as_uint(a), ub = __float_as_uint(b);
    asm("mov.b64 %0, {%1, %2};" : "=l"(r) : "r"(ua), "r"(ub));
    return r;
}
__device__ __forceinline__ void unpackf2(unsigned long long v, float& a, float& b) {
    unsigned ua, ub;
    asm("mov.b64 {%0, %1}, %2;" : "=r"(ua), "=r"(ub) : "l"(v));
    a = __uint_as_float(ua); b = __uint_as_float(ub);
}
__device__ __forceinline__ unsigned long long addf2(unsigned long long a, unsigned long long b) {
    unsigned long long r;
    asm("add.rn.f32x2 %0, %1, %2;" : "=l"(r) : "l"(a), "l"(b));
    return r;
}
__device__ __forceinline__ unsigned long long mulf2(unsigned long long a, unsigned long long b) {
    unsigned long long r;
    asm("mul.rn.f32x2 %0, %1, %2;" : "=l"(r) : "l"(a), "l"(b));
    return r;
}
__device__ __forceinline__ void fmaf2(unsigned long long& acc, unsigned long long a,
                                      unsigned long long b) {
    asm("fma.rn.f32x2 %0, %1, %2, %0;" : "+l"(acc) : "l"(a), "l"(b));
}

// ---------------------------------------------------------------------------
// FPS — R10 verbatim (best measured: 312.6us). One block/batch, 512 threads
// x 8 points (4 f32x2 pairs), IN-LOOP argmax interleaved with distance math,
// REDUX.SYNC reductions, one barrier + parity partials, float4 centroid LDG.
// Distances (dx^2+dy^2)+dz^2 all .rn == reference; first-index tie-break.
// ---------------------------------------------------------------------------
__global__ __launch_bounds__(512) void fps_kernel(float* __restrict__ newxyz) {
    const int b = blockIdx.x;
    const int tid = threadIdx.x;
    const int lane = tid & 31;
    const int w = tid >> 5;                 // 16 warps
    __shared__ unsigned long long part[2][16];

    const float4* xb4 = g_xyz4 + (size_t)b * NN;
    unsigned long long pxp[4], pyp[4], pzp[4];
    float dist[8];
#pragma unroll
    for (int jp = 0; jp < 4; jp++) {
        float4 f0 = __ldg(xb4 + tid + (2 * jp) * 512);
        float4 f1 = __ldg(xb4 + tid + (2 * jp + 1) * 512);
        pxp[jp] = packf2(f0.x, f1.x);
        pyp[jp] = packf2(f0.y, f1.y);
        pzp[jp] = packf2(f0.z, f1.z);
        dist[2 * jp] = 1e10f;
        dist[2 * jp + 1] = 1e10f;
    }

    int far = 0;
    for (int it = 0; it < SP; it++) {
        const int p = it & 1;
        float4 cen = __ldg(xb4 + far);      // 1 LDG.128 on the critical path
        if (tid == 0) {
            size_t o = ((size_t)b * SP + it) * 3;
            newxyz[o] = cen.x; newxyz[o + 1] = cen.y; newxyz[o + 2] = cen.z;
        }
        unsigned long long ncx = packf2(-cen.x, -cen.x);
        unsigned long long ncy = packf2(-cen.y, -cen.y);
        unsigned long long ncz = packf2(-cen.z, -cen.z);

        float bd = -1.0f;
        int bj = 0;
#pragma unroll
        for (int jp = 0; jp < 4; jp++) {
            unsigned long long dx = addf2(pxp[jp], ncx);   // a-b == a+(-b) exactly
            unsigned long long dy = addf2(pyp[jp], ncy);
            unsigned long long dz = addf2(pzp[jp], ncz);
            unsigned long long s = addf2(mulf2(dx, dx), mulf2(dy, dy));
            s = addf2(s, mulf2(dz, dz));
            float d0, d1;
            unpackf2(s, d0, d1);
            d0 = fminf(dist[2 * jp], d0);
            d1 = fminf(dist[2 * jp + 1], d1);
            dist[2 * jp] = d0;
            dist[2 * jp + 1] = d1;
            if (d0 > bd) { bd = d0; bj = 2 * jp; }       // strict > keeps earliest j
            if (d1 > bd) { bd = d1; bj = 2 * jp + 1; }
        }
        unsigned gidx = (unsigned)(tid + bj * 512);
        unsigned ub = __float_as_uint(bd);               // positive floats monotone as u32
        unsigned m = __reduce_max_sync(FULLM, ub);
        unsigned key = (ub == m) ? gidx : 0x7fffffffu;
        unsigned mi = __reduce_min_sync(FULLM, key);
        if (lane == 0) part[p][w] = ((unsigned long long)m << 32) | mi;
        __syncthreads();
        unsigned long long v = part[p][lane & 15];       // dup lanes harmless for max/min
        unsigned um = (unsigned)(v >> 32);
        unsigned ui = (unsigned)v;
        unsigned m2 = __reduce_max_sync(FULLM, um);
        unsigned key2 = (um == m2) ? ui : 0x7fffffffu;
        far = (int)__reduce_min_sync(FULLM, key2);
        // no second barrier: parity double-buffer
    }
}

// ---------------------------------------------------------------------------
// Ball query: one warp per center; 64 points per loop iteration via float4
// loads. First KS hits in ascending index order.
// ---------------------------------------------------------------------------
__global__ __launch_bounds__(128) void ballquery_kernel(const float* __restrict__ newxyz) {
    int gw = blockIdx.x * 4 + (threadIdx.x >> 5);
    int lane = threadIdx.x & 31;
    int b = gw >> 10;
    int s = gw & 1023;
    const float4* xb4 = g_xyz4 + (size_t)b * NN;
    size_t ci = (size_t)b * SP + s;
    float cx = newxyz[ci * 3], cy = newxyz[ci * 3 + 1], cz = newxyz[ci * 3 + 2];
    int* gp = g_gidx + ci * KS;
    const unsigned lm = (1u << lane) - 1u;

    int count = 0, first = -1;
    for (int base = 0; base < NN; base += 64) {
        int j0 = base + lane;
        int j1 = j0 + 32;
        float4 p0 = __ldg(xb4 + j0);
        float4 p1 = __ldg(xb4 + j1);
        float da = __fadd_rn(__fadd_rn(__fmul_rn(__fsub_rn(cx, p0.x), __fsub_rn(cx, p0.x)),
                                       __fmul_rn(__fsub_rn(cy, p0.y), __fsub_rn(cy, p0.y))),
                             __fmul_rn(__fsub_rn(cz, p0.z), __fsub_rn(cz, p0.z)));
        float db = __fadd_rn(__fadd_rn(__fmul_rn(__fsub_rn(cx, p1.x), __fsub_rn(cx, p1.x)),
                                       __fmul_rn(__fsub_rn(cy, p1.y), __fsub_rn(cy, p1.y))),
                             __fmul_rn(__fsub_rn(cz, p1.z), __fsub_rn(cz, p1.z)));
        bool va = !(da > 0.04f);
        bool vb = !(db > 0.04f);
        unsigned m0 = __ballot_sync(FULLM, va);
        unsigned m1 = __ballot_sync(FULLM, vb);
        if (first < 0) {
            if (m0) first = base + __ffs(m0) - 1;
            else if (m1) first = base + 32 + __ffs(m1) - 1;
        }
        int pos0 = count + __popc(m0 & lm);
        if (va && pos0 < KS) gp[pos0] = j0;
        int c0 = count + __popc(m0);
        int pos1 = c0 + __popc(m1 & lm);
        if (vb && pos1 < KS) gp[pos1] = j1;
        count = c0 + __popc(m1);
        if (count >= KS) break;
    }
    if (lane >= count) gp[lane] = first;
}

// ---------------------------------------------------------------------------
// Prep: fold BN into scale/bias; transpose weights to [c][o]; g_dw.
// ---------------------------------------------------------------------------
__global__ void prep_kernel(
    const float* __restrict__ w0, const float* __restrict__ b0,
    const float* __restrict__ g0, const float* __restrict__ be0,
    const float* __restrict__ m0, const float* __restrict__ v0,
    const float* __restrict__ w1, const float* __restrict__ b1,
    const float* __restrict__ g1, const float* __restrict__ be1,
    const float* __restrict__ m1, const float* __restrict__ v1,
    const float* __restrict__ w2, const float* __restrict__ b2,
    const float* __restrict__ g2, const float* __restrict__ be2,
    const float* __restrict__ m2, const float* __restrict__ v2) {
    int t = threadIdx.x;  // 256
    {
        float g, bb, be, m, v;
        if (t < 64)       { int o = t;       g = g0[o]; bb = b0[o]; be = be0[o]; m = m0[o]; v = v0[o]; }
        else if (t < 128) { int o = t - 64;  g = g1[o]; bb = b1[o]; be = be1[o]; m = m1[o]; v = v1[o]; }
        else              { int o = t - 128; g = g2[o]; bb = b2[o]; be = be2[o]; m = m2[o]; v = v2[o]; }
        float sc = g * rsqrtf(v + 1e-5f);
        g_scbi[t] = sc;
        g_scbi[256 + t] = fmaf(sc, bb - m, be);
    }
    if (t < 192) {  // g_dw[c][o] = sc0[o] * w0[o][c], c<3 (sc recomputed, no bar)
        int c = t >> 6, o = t & 63;
        g_dw[t] = g0[o] * rsqrtf(v0[o] + 1e-5f) * w0[o * 67 + c];
    }
    for (int i = t; i < 64 * 67; i += 256) { int o = i / 67, c = i - o * 67; g_w0t[c * 64 + o] = w0[i]; }
    for (int i = t; i < 64 * 64; i += 256) { int o = i >> 6, c = i & 63; g_w1t[c * 64 + o] = w1[i]; }
    for (int i = t; i < 128 * 64; i += 256) { int o = i >> 6, c = i & 63; g_w2t[c * 128 + o] = w2[i]; }
}

// ---------------------------------------------------------------------------
// Z precompute: Z[j][o] = sc0[o]*(W0 @ [xyz_j; pts_j])[o] + bi0[o]  (no relu).
// Also fills this block's 32 g_xyz4 entries (folds the old xyz4_kernel).
// ---------------------------------------------------------------------------
__global__ __launch_bounds__(128) void zprep_kernel(const float* __restrict__ xyz,
                                                    const float* __restrict__ points) {
    __shared__ __align__(16) float sF[67 * XS];
    __shared__ __align__(16) float sB[32 * 64];   // [k][o] for coalesced STG
    int t = threadIdx.x;
    int lane = t & 31, kg = t >> 5;
    int b = blockIdx.x >> 7;
    int j0 = (blockIdx.x & 127) * 32;
    const size_t rowb = (size_t)b * NN + j0;

    if (t < 96) { int c = t / 32, k = t % 32; sF[c * XS + k] = xyz[(rowb + k) * 3 + c]; }
    for (int i = t; i < 32 * 64; i += 128) {
        int c = i & 63, k = i >> 6;
        sF[(3 + c) * XS + k] = points[(rowb + k) * DD + c];
    }
    if (t < 32) {   // fold xyz4: one float4 store per point (coalesced)
        int k = t;
        g_xyz4[rowb + k] = make_float4(xyz[(rowb + k) * 3],
                                       xyz[(rowb + k) * 3 + 1],
                                       xyz[(rowb + k) * 3 + 2], 0.f);
    }
    __syncthreads();

    unsigned long long acc[2][4];
#pragma unroll
    for (int i = 0; i < 2; i++)
#pragma unroll
        for (int jp = 0; jp < 4; jp++) acc[i][jp] = 0ull;
    const float* xbase = sF + kg * 8;
#pragma unroll 4
    for (int c = 0; c < 67; c++) {
        ulonglong2 xv01 = *(const ulonglong2*)(xbase + c * XS);
        ulonglong2 xv23 = *(const ulonglong2*)(xbase + c * XS + 4);
        float2 wv = *(const float2*)(g_w0t + c * 64 + 2 * lane);
        unsigned long long w0p = packf2(wv.x, wv.x);
        unsigned long long w1p = packf2(wv.y, wv.y);
        fmaf2(acc[0][0], xv01.x, w0p); fmaf2(acc[0][1], xv01.y, w0p);
        fmaf2(acc[0][2], xv23.x, w0p); fmaf2(acc[0][3], xv23.y, w0p);
        fmaf2(acc[1][0], xv01.x, w1p); fmaf2(acc[1][1], xv01.y, w1p);
        fmaf2(acc[1][2], xv23.x, w1p); fmaf2(acc[1][3], xv23.y, w1p);
    }
    {
        int o = 2 * lane;
        float s0 = g_scbi[o], b0_ = g_scbi[256 + o];
        float s1 = g_scbi[o + 1], b1_ = g_scbi[256 + o + 1];
#pragma unroll
        for (int jp = 0; jp < 4; jp++) {
            float a0, a1, c0, c1;
            unpackf2(acc[0][jp], a0, a1);
            unpackf2(acc[1][jp], c0, c1);
            int k = kg * 8 + 2 * jp;
            *(float2*)(sB + k * 64 + o) = make_float2(fmaf(a0, s0, b0_), fmaf(c0, s1, b1_));
            *(float2*)(sB + (k + 1) * 64 + o) = make_float2(fmaf(a1, s0, b0_), fmaf(c1, s1, b1_));
        }
    }
    __syncthreads();
    for (int i = t; i < 32 * 64; i += 128) {
        int o = i & 63, k = i >> 6;
        g_z[(rowb + k) * 64 + o] = sB[k * 64 + o];
    }
}

// ---------------------------------------------------------------------------
// MLP layers l1/l2 — R10 verbatim (scalar-weight loads + in-register pack).
// Activations [c][k] stride XS; warp kg owns k kg*8..+7.
// ---------------------------------------------------------------------------
__device__ __forceinline__ void layer64(const float* __restrict__ X,
                                        const float* __restrict__ Wg,
                                        float* __restrict__ Y,
                                        const float* __restrict__ scp,
                                        const float* __restrict__ bip,
                                        int kg, int lane) {
    unsigned long long acc[2][4];
#pragma unroll
    for (int i = 0; i < 2; i++)
#pragma unroll
        for (int jp = 0; jp < 4; jp++) acc[i][jp] = 0ull;
    const float* xbase = X + kg * 8;
#pragma unroll 4
    for (int c = 0; c < 64; c++) {
        ulonglong2 xv01 = *(const ulonglong2*)(xbase + c * XS);
        ulonglong2 xv23 = *(const ulonglong2*)(xbase + c * XS + 4);
        float2 wv = *(const float2*)(Wg + c * 64 + 2 * lane);
        unsigned long long w0p = packf2(wv.x, wv.x);
        unsigned long long w1p = packf2(wv.y, wv.y);
        fmaf2(acc[0][0], xv01.x, w0p); fmaf2(acc[0][1], xv01.y, w0p);
        fmaf2(acc[0][2], xv23.x, w0p); fmaf2(acc[0][3], xv23.y, w0p);
        fmaf2(acc[1][0], xv01.x, w1p); fmaf2(acc[1][1], xv01.y, w1p);
        fmaf2(acc[1][2], xv23.x, w1p); fmaf2(acc[1][3], xv23.y, w1p);
    }
#pragma unroll
    for (int i = 0; i < 2; i++) {
        int o = 2 * lane + i;
        float s = scp[o], bb = bip[o];
        float* yr = Y + o * XS + kg * 8;
#pragma unroll
        for (int jp = 0; jp < 4; jp++) {
            float v0, v1;
            unpackf2(acc[i][jp], v0, v1);
            yr[2 * jp] = fmaxf(fmaf(v0, s, bb), 0.f);
            yr[2 * jp + 1] = fmaxf(fmaf(v1, s, bb), 0.f);
        }
    }
}

__device__ __forceinline__ void layer128max(const float* __restrict__ X,
                                            const float* __restrict__ Wg,
                                            float* __restrict__ spm,
                                            const float* __restrict__ scp,
                                            const float* __restrict__ bip,
                                            int kg, int lane) {
    unsigned long long acc[4][4];
#pragma unroll
    for (int i = 0; i < 4; i++)
#pragma unroll
        for (int jp = 0; jp < 4; jp++) acc[i][jp] = 0ull;
    const float* xbase = X + kg * 8;
#pragma unroll 2
    for (int c = 0; c < 64; c++) {
        ulonglong2 xv01 = *(const ulonglong2*)(xbase + c * XS);
        ulonglong2 xv23 = *(const ulonglong2*)(xbase + c * XS + 4);
        float4 wv = *(const float4*)(Wg + c * 128 + 4 * lane);
        unsigned long long wp0 = packf2(wv.x, wv.x);
        unsigned long long wp1 = packf2(wv.y, wv.y);
        unsigned long long wp2 = packf2(wv.z, wv.z);
        unsigned long long wp3 = packf2(wv.w, wv.w);
        fmaf2(acc[0][0], xv01.x, wp0); fmaf2(acc[0][1], xv01.y, wp0);
        fmaf2(acc[0][2], xv23.x, wp0); fmaf2(acc[0][3], xv23.y, wp0);
        fmaf2(acc[1][0], xv01.x, wp1); fmaf2(acc[1][1], xv01.y, wp1);
        fmaf2(acc[1][2], xv23.x, wp1); fmaf2(acc[1][3], xv23.y, wp1);
        fmaf2(acc[2][0], xv01.x, wp2); fmaf2(acc[2][1], xv01.y, wp2);
        fmaf2(acc[2][2], xv23.x, wp2); fmaf2(acc[2][3], xv23.y, wp2);
        fmaf2(acc[3][0], xv01.x, wp3); fmaf2(acc[3][1], xv01.y, wp3);
        fmaf2(acc[3][2], xv23.x, wp3); fmaf2(acc[3][3], xv23.y, wp3);
    }
#pragma unroll
    for (int i = 0; i < 4; i++) {
        int o = 4 * lane + i;
        float s = scp[o], bb = bip[o];
        float mx = 0.f;  // relu >= 0
#pragma unroll
        for (int jp = 0; jp < 4; jp++) {
            float v0, v1;
            unpackf2(acc[i][jp], v0, v1);
            mx = fmaxf(mx, fmaf(v0, s, bb));
            mx = fmaxf(mx, fmaf(v1, s, bb));
        }
        spm[kg * 128 + o] = mx;
    }
}

// ---------------------------------------------------------------------------
// MLP: gather pipelined one center ahead; sgid in registers + shfl; dvec
// per-thread from hoisted g_dw registers. 2 barriers per center. (R10)
// ---------------------------------------------------------------------------
__global__ __launch_bounds__(128) void mlp_kernel(const float* __restrict__ newxyz,
                                                  float* __restrict__ outp) {
    __shared__ __align__(16) float sA[64 * XS];
    __shared__ __align__(16) float sB[64 * XS];
    __shared__ float spm[512];

    int t = threadIdx.x;
    int lane = t & 31, kg = t >> 5;
    int b = blockIdx.x >> 7;
    int sbase = (blockIdx.x & 127) * NC;
    const float* sc = g_scbi;
    const float* bi = g_scbi + 256;
    const float* zb = g_z + (size_t)b * NN * 64;
    const int f4 = (t & 15) * 4;          // base channel for this thread
    const int kb = t >> 4;                // base k (0..7)

    const float4 dwx = *(const float4*)(g_dw + f4);
    const float4 dwy = *(const float4*)(g_dw + 64 + f4);
    const float4 dwz = *(const float4*)(g_dw + 128 + f4);

    size_t ci0 = (size_t)b * SP + sbase;

    int sgid_r = g_gidx[ci0 * KS + lane];
    float4 dv;
    {
        float cx = __ldg(newxyz + ci0 * 3);
        float cy = __ldg(newxyz + ci0 * 3 + 1);
        float cz = __ldg(newxyz + ci0 * 3 + 2);
        dv.x = -(dwx.x * cx + dwy.x * cy + dwz.x * cz);
        dv.y = -(dwx.y * cx + dwy.y * cy + dwz.y * cz);
        dv.z = -(dwx.z * cx + dwy.z * cy + dwz.z * cz);
        dv.w = -(dwx.w * cx + dwy.w * cy + dwz.w * cz);
    }
    float4 zr[4];
#pragma unroll
    for (int j = 0; j < 4; j++) {
        int row = __shfl_sync(FULLM, sgid_r, kb + 8 * j);
        zr[j] = *(const float4*)(zb + (size_t)row * 64 + f4);
    }

    for (int cc = 0; cc < NC; cc++) {
        size_t ci = ci0 + cc;
#pragma unroll
        for (int j = 0; j < 4; j++) {
            int k = kb + 8 * j;
            sA[(f4 + 0) * XS + k] = fmaxf(zr[j].x + dv.x, 0.f);
            sA[(f4 + 1) * XS + k] = fmaxf(zr[j].y + dv.y, 0.f);
            sA[(f4 + 2) * XS + k] = fmaxf(zr[j].z + dv.z, 0.f);
            sA[(f4 + 3) * XS + k] = fmaxf(zr[j].w + dv.w, 0.f);
        }
        if (cc + 1 < NC) {
            size_t cin = ci + 1;
            sgid_r = g_gidx[cin * KS + lane];
            float cx = __ldg(newxyz + cin * 3);
            float cy = __ldg(newxyz + cin * 3 + 1);
            float cz = __ldg(newxyz + cin * 3 + 2);
            dv.x = -(dwx.x * cx + dwy.x * cy + dwz.x * cz);
            dv.y = -(dwx.y * cx + dwy.y * cy + dwz.y * cz);
            dv.z = -(dwx.z * cx + dwy.z * cy + dwz.z * cz);
            dv.w = -(dwx.w * cx + dwy.w * cy + dwz.w * cz);
#pragma unroll
            for (int j = 0; j < 4; j++) {
                int row = __shfl_sync(FULLM, sgid_r, kb + 8 * j);
                zr[j] = *(const float4*)(zb + (size_t)row * 64 + f4);
            }
        }
        __syncthreads();

        layer64(sA, g_w1t, sB, sc + 64, bi + 64, kg, lane);
        __syncwarp();   // sB k-slices warp-local; order STS->LDS within warp
        layer128max(sB, g_w2t, spm, sc + 128, bi + 128, kg, lane);
        __syncthreads();

        float r = fmaxf(fmaxf(spm[t], spm[128 + t]), fmaxf(spm[256 + t], spm[384 + t]));
        outp[ci * 128 + t] = r;
    }
}

// ---------------------------------------------------------------------------
// Single-stream, serial (overlap measured as a loser in R6/R7).
// ---------------------------------------------------------------------------
extern "C" void kernel_launch(void* const* d_in, const int* in_sizes, int n_in,
                              void* d_out, int out_size) {
    const float* xyz = (const float*)d_in[0];
    const float* points = (const float*)d_in[1];
    const float* w0 = (const float*)d_in[2];
    const float* b0 = (const float*)d_in[3];
    const float* g0 = (const float*)d_in[4];
    const float* be0 = (const float*)d_in[5];
    const float* m0 = (const float*)d_in[6];
    const float* v0 = (const float*)d_in[7];
    const float* w1 = (const float*)d_in[8];
    const float* b1 = (const float*)d_in[9];
    const float* g1 = (const float*)d_in[10];
    const float* be1 = (const float*)d_in[11];
    const float* m1 = (const float*)d_in[12];
    const float* v1 = (const float*)d_in[13];
    const float* w2 = (const float*)d_in[14];
    const float* b2 = (const float*)d_in[15];
    const float* g2 = (const float*)d_in[16];
    const float* be2 = (const float*)d_in[17];
    const float* m2 = (const float*)d_in[18];
    const float* v2 = (const float*)d_in[19];

    float* out = (float*)d_out;
    float* newxyz = out;                          // [B, SP, 3]
    float* newpts = out + (size_t)BB * SP * 3;    // [B, SP, 128]

    prep_kernel<<<1, 256>>>(w0, b0, g0, be0, m0, v0,
                            w1, b1, g1, be1, m1, v1,
                            w2, b2, g2, be2, m2, v2);
    zprep_kernel<<<BB * NN / 32, 128>>>(xyz, points);
    fps_kernel<<<BB, 512>>>(newxyz);
    ballquery_kernel<<<BB * SP / 4, 128>>>(newxyz);
    mlp_kernel<<<BB * SP / NC, 128>>>(newxyz, newpts);
}

// round 15
// speedup vs baseline: 1.3647x; 1.0020x over previous
#include <cuda_runtime.h>

#define BB 8
#define NN 4096
#define DD 64
#define SP 1024   // NPOINT
#define KS 32     // NSAMPLE
#define NC 8      // centers per MLP block
#define XS 36     // activation row stride (floats); 16B-aligned rows
#define FULLM 0xffffffffu

__device__ int g_gidx[BB * SP * KS];
__device__ float g_w0t[67 * 64];            // [c][o]
__device__ float g_w1t[64 * 64];            // [c][o]
__device__ float g_w2t[64 * 128];           // [c][o]
__device__ float g_scbi[512];               // sc[256] | bi[256]
__device__ float g_dw[3 * 64];              // sc0[o]*W0[o][c], c<3
__device__ float g_z[BB * NN * 64];         // precomputed layer0 (abs coords), 8MB
__device__ float4 g_xyz4[BB * NN];          // xyz as float4 (w=0), filled by zprep

// ---------------- f32x2 packed helpers (per-half .rn == scalar .rn) --------
__device__ __forceinline__ unsigned long long packf2(float a, float b) {
    unsigned long long r;
    unsigned ua = __float_as_uint(a), ub = __float_as_uint(b);
    asm("mov.b64 %0, {%1, %2};" : "=l"(r) : "r"(ua), "r"(ub));
    return r;
}
__device__ __forceinline__ void unpackf2(unsigned long long v, float& a, float& b) {
    unsigned ua, ub;
    asm("mov.b64 {%0, %1}, %2;" : "=r"(ua), "=r"(ub) : "l"(v));
    a = __uint_as_float(ua); b = __uint_as_float(ub);
}
__device__ __forceinline__ unsigned long long addf2(unsigned long long a, unsigned long long b) {
    unsigned long long r;
    asm("add.rn.f32x2 %0, %1, %2;" : "=l"(r) : "l"(a), "l"(b));
    return r;
}
__device__ __forceinline__ unsigned long long mulf2(unsigned long long a, unsigned long long b) {
    unsigned long long r;
    asm("mul.rn.f32x2 %0, %1, %2;" : "=l"(r) : "l"(a), "l"(b));
    return r;
}
__device__ __forceinline__ void fmaf2(unsigned long long& acc, unsigned long long a,
                                      unsigned long long b) {
    asm("fma.rn.f32x2 %0, %1, %2, %0;" : "+l"(acc) : "l"(a), "l"(b));
}

// ---------------------------------------------------------------------------
// FPS: R10/R14 structure, but per-iteration newxyz STG replaced by a 1-word
// STS of `far` (history buffer); centroids written in a final phase from the
// history. Otherwise verbatim: 512 threads x 8 points, in-loop argmax,
// REDUX.SYNC, one barrier + parity partials, float4 centroid LDG.
// Distances (dx^2+dy^2)+dz^2 all .rn == reference; first-index tie-break.
// ---------------------------------------------------------------------------
__global__ __launch_bounds__(512) void fps_kernel(float* __restrict__ newxyz) {
    const int b = blockIdx.x;
    const int tid = threadIdx.x;
    const int lane = tid & 31;
    const int w = tid >> 5;                 // 16 warps
    __shared__ unsigned long long part[2][16];
    __shared__ int hist[SP];                // selected index per iteration

    const float4* xb4 = g_xyz4 + (size_t)b * NN;
    unsigned long long pxp[4], pyp[4], pzp[4];
    float dist[8];
#pragma unroll
    for (int jp = 0; jp < 4; jp++) {
        float4 f0 = __ldg(xb4 + tid + (2 * jp) * 512);
        float4 f1 = __ldg(xb4 + tid + (2 * jp + 1) * 512);
        pxp[jp] = packf2(f0.x, f1.x);
        pyp[jp] = packf2(f0.y, f1.y);
        pzp[jp] = packf2(f0.z, f1.z);
        dist[2 * jp] = 1e10f;
        dist[2 * jp + 1] = 1e10f;
    }

    int far = 0;
    for (int it = 0; it < SP; it++) {
        const int p = it & 1;
        float4 cen = __ldg(xb4 + far);      // 1 LDG.128 on the critical path
        if (tid == 0) hist[it] = far;       // 1 STS.32 (replaces 3 STG.32)
        unsigned long long ncx = packf2(-cen.x, -cen.x);
        unsigned long long ncy = packf2(-cen.y, -cen.y);
        unsigned long long ncz = packf2(-cen.z, -cen.z);

        float bd = -1.0f;
        int bj = 0;
#pragma unroll
        for (int jp = 0; jp < 4; jp++) {
            unsigned long long dx = addf2(pxp[jp], ncx);   // a-b == a+(-b) exactly
            unsigned long long dy = addf2(pyp[jp], ncy);
            unsigned long long dz = addf2(pzp[jp], ncz);
            unsigned long long s = addf2(mulf2(dx, dx), mulf2(dy, dy));
            s = addf2(s, mulf2(dz, dz));
            float d0, d1;
            unpackf2(s, d0, d1);
            d0 = fminf(dist[2 * jp], d0);
            d1 = fminf(dist[2 * jp + 1], d1);
            dist[2 * jp] = d0;
            dist[2 * jp + 1] = d1;
            if (d0 > bd) { bd = d0; bj = 2 * jp; }       // strict > keeps earliest j
            if (d1 > bd) { bd = d1; bj = 2 * jp + 1; }
        }
        unsigned gidx = (unsigned)(tid + bj * 512);
        unsigned ub = __float_as_uint(bd);               // positive floats monotone as u32
        unsigned m = __reduce_max_sync(FULLM, ub);
        unsigned key = (ub == m) ? gidx : 0x7fffffffu;
        unsigned mi = __reduce_min_sync(FULLM, key);
        if (lane == 0) part[p][w] = ((unsigned long long)m << 32) | mi;
        __syncthreads();
        unsigned long long v = part[p][lane & 15];       // dup lanes harmless for max/min
        unsigned um = (unsigned)(v >> 32);
        unsigned ui = (unsigned)v;
        unsigned m2 = __reduce_max_sync(FULLM, um);
        unsigned key2 = (um == m2) ? ui : 0x7fffffffu;
        far = (int)__reduce_min_sync(FULLM, key2);
        // no second barrier: parity double-buffer
    }
    __syncthreads();
    // final phase: write all centroids from history (off the serial loop)
    for (int it = tid; it < SP; it += 512) {
        float4 cen = __ldg(xb4 + hist[it]);
        size_t o = ((size_t)b * SP + it) * 3;
        newxyz[o] = cen.x; newxyz[o + 1] = cen.y; newxyz[o + 2] = cen.z;
    }
}

// ---------------------------------------------------------------------------
// Ball query: one warp per center; 128 points per loop iteration (4 float4
// LDGs + 4 ballots). First KS hits in ascending index order (prefix chained
// across the 4 masks).
// ---------------------------------------------------------------------------
__global__ __launch_bounds__(128) void ballquery_kernel(const float* __restrict__ newxyz) {
    int gw = blockIdx.x * 4 + (threadIdx.x >> 5);
    int lane = threadIdx.x & 31;
    int b = gw >> 10;
    int s = gw & 1023;
    const float4* xb4 = g_xyz4 + (size_t)b * NN;
    size_t ci = (size_t)b * SP + s;
    float cx = newxyz[ci * 3], cy = newxyz[ci * 3 + 1], cz = newxyz[ci * 3 + 2];
    int* gp = g_gidx + ci * KS;
    const unsigned lm = (1u << lane) - 1u;

    int count = 0, first = -1;
    for (int base = 0; base < NN; base += 128) {
        unsigned msk[4];
        bool val[4];
#pragma unroll
        for (int q = 0; q < 4; q++) {
            int j = base + 32 * q + lane;
            float4 pt = __ldg(xb4 + j);
            float d = __fadd_rn(
                __fadd_rn(__fmul_rn(__fsub_rn(cx, pt.x), __fsub_rn(cx, pt.x)),
                          __fmul_rn(__fsub_rn(cy, pt.y), __fsub_rn(cy, pt.y))),
                __fmul_rn(__fsub_rn(cz, pt.z), __fsub_rn(cz, pt.z)));
            val[q] = !(d > 0.04f);
            msk[q] = __ballot_sync(FULLM, val[q]);
        }
#pragma unroll
        for (int q = 0; q < 4; q++) {
            if (first < 0 && msk[q]) first = base + 32 * q + __ffs(msk[q]) - 1;
            int pos = count + __popc(msk[q] & lm);
            if (val[q] && pos < KS) gp[pos] = base + 32 * q + lane;
            count += __popc(msk[q]);
        }
        if (count >= KS) break;
    }
    if (lane >= count) gp[lane] = first;
}

// ---------------------------------------------------------------------------
// Prep: fold BN into scale/bias; transpose weights to [c][o]; g_dw.
// ---------------------------------------------------------------------------
__global__ void prep_kernel(
    const float* __restrict__ w0, const float* __restrict__ b0,
    const float* __restrict__ g0, const float* __restrict__ be0,
    const float* __restrict__ m0, const float* __restrict__ v0,
    const float* __restrict__ w1, const float* __restrict__ b1,
    const float* __restrict__ g1, const float* __restrict__ be1,
    const float* __restrict__ m1, const float* __restrict__ v1,
    const float* __restrict__ w2, const float* __restrict__ b2,
    const float* __restrict__ g2, const float* __restrict__ be2,
    const float* __restrict__ m2, const float* __restrict__ v2) {
    int t = threadIdx.x;  // 256
    {
        float g, bb, be, m, v;
        if (t < 64)       { int o = t;       g = g0[o]; bb = b0[o]; be = be0[o]; m = m0[o]; v = v0[o]; }
        else if (t < 128) { int o = t - 64;  g = g1[o]; bb = b1[o]; be = be1[o]; m = m1[o]; v = v1[o]; }
        else              { int o = t - 128; g = g2[o]; bb = b2[o]; be = be2[o]; m = m2[o]; v = v2[o]; }
        float sc = g * rsqrtf(v + 1e-5f);
        g_scbi[t] = sc;
        g_scbi[256 + t] = fmaf(sc, bb - m, be);
    }
    if (t < 192) {  // g_dw[c][o] = sc0[o] * w0[o][c], c<3 (sc recomputed, no bar)
        int c = t >> 6, o = t & 63;
        g_dw[t] = g0[o] * rsqrtf(v0[o] + 1e-5f) * w0[o * 67 + c];
    }
    for (int i = t; i < 64 * 67; i += 256) { int o = i / 67, c = i - o * 67; g_w0t[c * 64 + o] = w0[i]; }
    for (int i = t; i < 64 * 64; i += 256) { int o = i >> 6, c = i & 63; g_w1t[c * 64 + o] = w1[i]; }
    for (int i = t; i < 128 * 64; i += 256) { int o = i >> 6, c = i & 63; g_w2t[c * 128 + o] = w2[i]; }
}

// ---------------------------------------------------------------------------
// Z precompute: Z[j][o] = sc0[o]*(W0 @ [xyz_j; pts_j])[o] + bi0[o]  (no relu).
// Also fills this block's 32 g_xyz4 entries (folds the old xyz4_kernel).
// ---------------------------------------------------------------------------
__global__ __launch_bounds__(128) void zprep_kernel(const float* __restrict__ xyz,
                                                    const float* __restrict__ points) {
    __shared__ __align__(16) float sF[67 * XS];
    __shared__ __align__(16) float sB[32 * 64];   // [k][o] for coalesced STG
    int t = threadIdx.x;
    int lane = t & 31, kg = t >> 5;
    int b = blockIdx.x >> 7;
    int j0 = (blockIdx.x & 127) * 32;
    const size_t rowb = (size_t)b * NN + j0;

    if (t < 96) { int c = t / 32, k = t % 32; sF[c * XS + k] = xyz[(rowb + k) * 3 + c]; }
    for (int i = t; i < 32 * 64; i += 128) {
        int c = i & 63, k = i >> 6;
        sF[(3 + c) * XS + k] = points[(rowb + k) * DD + c];
    }
    if (t < 32) {   // fold xyz4: one float4 store per point (coalesced)
        int k = t;
        g_xyz4[rowb + k] = make_float4(xyz[(rowb + k) * 3],
                                       xyz[(rowb + k) * 3 + 1],
                                       xyz[(rowb + k) * 3 + 2], 0.f);
    }
    __syncthreads();

    unsigned long long acc[2][4];
#pragma unroll
    for (int i = 0; i < 2; i++)
#pragma unroll
        for (int jp = 0; jp < 4; jp++) acc[i][jp] = 0ull;
    const float* xbase = sF + kg * 8;
#pragma unroll 4
    for (int c = 0; c < 67; c++) {
        ulonglong2 xv01 = *(const ulonglong2*)(xbase + c * XS);
        ulonglong2 xv23 = *(const ulonglong2*)(xbase + c * XS + 4);
        float2 wv = *(const float2*)(g_w0t + c * 64 + 2 * lane);
        unsigned long long w0p = packf2(wv.x, wv.x);
        unsigned long long w1p = packf2(wv.y, wv.y);
        fmaf2(acc[0][0], xv01.x, w0p); fmaf2(acc[0][1], xv01.y, w0p);
        fmaf2(acc[0][2], xv23.x, w0p); fmaf2(acc[0][3], xv23.y, w0p);
        fmaf2(acc[1][0], xv01.x, w1p); fmaf2(acc[1][1], xv01.y, w1p);
        fmaf2(acc[1][2], xv23.x, w1p); fmaf2(acc[1][3], xv23.y, w1p);
    }
    {
        int o = 2 * lane;
        float s0 = g_scbi[o], b0_ = g_scbi[256 + o];
        float s1 = g_scbi[o + 1], b1_ = g_scbi[256 + o + 1];
#pragma unroll
        for (int jp = 0; jp < 4; jp++) {
            float a0, a1, c0, c1;
            unpackf2(acc[0][jp], a0, a1);
            unpackf2(acc[1][jp], c0, c1);
            int k = kg * 8 + 2 * jp;
            *(float2*)(sB + k * 64 + o) = make_float2(fmaf(a0, s0, b0_), fmaf(c0, s1, b1_));
            *(float2*)(sB + (k + 1) * 64 + o) = make_float2(fmaf(a1, s0, b0_), fmaf(c1, s1, b1_));
        }
    }
    __syncthreads();
    for (int i = t; i < 32 * 64; i += 128) {
        int o = i & 63, k = i >> 6;
        g_z[(rowb + k) * 64 + o] = sB[k * 64 + o];
    }
}

// ---------------------------------------------------------------------------
// MLP layers l1/l2 — R10 verbatim (scalar-weight loads + in-register pack).
// Activations [c][k] stride XS; warp kg owns k kg*8..+7.
// ---------------------------------------------------------------------------
__device__ __forceinline__ void layer64(const float* __restrict__ X,
                                        const float* __restrict__ Wg,
                                        float* __restrict__ Y,
                                        const float* __restrict__ scp,
                                        const float* __restrict__ bip,
                                        int kg, int lane) {
    unsigned long long acc[2][4];
#pragma unroll
    for (int i = 0; i < 2; i++)
#pragma unroll
        for (int jp = 0; jp < 4; jp++) acc[i][jp] = 0ull;
    const float* xbase = X + kg * 8;
#pragma unroll 4
    for (int c = 0; c < 64; c++) {
        ulonglong2 xv01 = *(const ulonglong2*)(xbase + c * XS);
        ulonglong2 xv23 = *(const ulonglong2*)(xbase + c * XS + 4);
        float2 wv = *(const float2*)(Wg + c * 64 + 2 * lane);
        unsigned long long w0p = packf2(wv.x, wv.x);
        unsigned long long w1p = packf2(wv.y, wv.y);
        fmaf2(acc[0][0], xv01.x, w0p); fmaf2(acc[0][1], xv01.y, w0p);
        fmaf2(acc[0][2], xv23.x, w0p); fmaf2(acc[0][3], xv23.y, w0p);
        fmaf2(acc[1][0], xv01.x, w1p); fmaf2(acc[1][1], xv01.y, w1p);
        fmaf2(acc[1][2], xv23.x, w1p); fmaf2(acc[1][3], xv23.y, w1p);
    }
#pragma unroll
    for (int i = 0; i < 2; i++) {
        int o = 2 * lane + i;
        float s = scp[o], bb = bip[o];
        float* yr = Y + o * XS + kg * 8;
#pragma unroll
        for (int jp = 0; jp < 4; jp++) {
            float v0, v1;
            unpackf2(acc[i][jp], v0, v1);
            yr[2 * jp] = fmaxf(fmaf(v0, s, bb), 0.f);
            yr[2 * jp + 1] = fmaxf(fmaf(v1, s, bb), 0.f);
        }
    }
}

__device__ __forceinline__ void layer128max(const float* __restrict__ X,
                                            const float* __restrict__ Wg,
                                            float* __restrict__ spm,
                                            const float* __restrict__ scp,
                                            const float* __restrict__ bip,
                                            int kg, int lane) {
    unsigned long long acc[4][4];
#pragma unroll
    for (int i = 0; i < 4; i++)
#pragma unroll
        for (int jp = 0; jp < 4; jp++) acc[i][jp] = 0ull;
    const float* xbase = X + kg * 8;
#pragma unroll 2
    for (int c = 0; c < 64; c++) {
        ulonglong2 xv01 = *(const ulonglong2*)(xbase + c * XS);
        ulonglong2 xv23 = *(const ulonglong2*)(xbase + c * XS + 4);
        float4 wv = *(const float4*)(Wg + c * 128 + 4 * lane);
        unsigned long long wp0 = packf2(wv.x, wv.x);
        unsigned long long wp1 = packf2(wv.y, wv.y);
        unsigned long long wp2 = packf2(wv.z, wv.z);
        unsigned long long wp3 = packf2(wv.w, wv.w);
        fmaf2(acc[0][0], xv01.x, wp0); fmaf2(acc[0][1], xv01.y, wp0);
        fmaf2(acc[0][2], xv23.x, wp0); fmaf2(acc[0][3], xv23.y, wp0);
        fmaf2(acc[1][0], xv01.x, wp1); fmaf2(acc[1][1], xv01.y, wp1);
        fmaf2(acc[1][2], xv23.x, wp1); fmaf2(acc[1][3], xv23.y, wp1);
        fmaf2(acc[2][0], xv01.x, wp2); fmaf2(acc[2][1], xv01.y, wp2);
        fmaf2(acc[2][2], xv23.x, wp2); fmaf2(acc[2][3], xv23.y, wp2);
        fmaf2(acc[3][0], xv01.x, wp3); fmaf2(acc[3][1], xv01.y, wp3);
        fmaf2(acc[3][2], xv23.x, wp3); fmaf2(acc[3][3], xv23.y, wp3);
    }
#pragma unroll
    for (int i = 0; i < 4; i++) {
        int o = 4 * lane + i;
        float s = scp[o], bb = bip[o];
        float mx = 0.f;  // relu >= 0
#pragma unroll
        for (int jp = 0; jp < 4; jp++) {
            float v0, v1;
            unpackf2(acc[i][jp], v0, v1);
            mx = fmaxf(mx, fmaf(v0, s, bb));
            mx = fmaxf(mx, fmaf(v1, s, bb));
        }
        spm[kg * 128 + o] = mx;
    }
}

// ---------------------------------------------------------------------------
// MLP: gather pipelined one center ahead; sgid in registers + shfl; dvec
// per-thread from hoisted g_dw registers. 2 barriers per center. (R10)
// ---------------------------------------------------------------------------
__global__ __launch_bounds__(128) void mlp_kernel(const float* __restrict__ newxyz,
                                                  float* __restrict__ outp) {
    __shared__ __align__(16) float sA[64 * XS];
    __shared__ __align__(16) float sB[64 * XS];
    __shared__ float spm[512];

    int t = threadIdx.x;
    int lane = t & 31, kg = t >> 5;
    int b = blockIdx.x >> 7;
    int sbase = (blockIdx.x & 127) * NC;
    const float* sc = g_scbi;
    const float* bi = g_scbi + 256;
    const float* zb = g_z + (size_t)b * NN * 64;
    const int f4 = (t & 15) * 4;          // base channel for this thread
    const int kb = t >> 4;                // base k (0..7)

    const float4 dwx = *(const float4*)(g_dw + f4);
    const float4 dwy = *(const float4*)(g_dw + 64 + f4);
    const float4 dwz = *(const float4*)(g_dw + 128 + f4);

    size_t ci0 = (size_t)b * SP + sbase;

    int sgid_r = g_gidx[ci0 * KS + lane];
    float4 dv;
    {
        float cx = __ldg(newxyz + ci0 * 3);
        float cy = __ldg(newxyz + ci0 * 3 + 1);
        float cz = __ldg(newxyz + ci0 * 3 + 2);
        dv.x = -(dwx.x * cx + dwy.x * cy + dwz.x * cz);
        dv.y = -(dwx.y * cx + dwy.y * cy + dwz.y * cz);
        dv.z = -(dwx.z * cx + dwy.z * cy + dwz.z * cz);
        dv.w = -(dwx.w * cx + dwy.w * cy + dwz.w * cz);
    }
    float4 zr[4];
#pragma unroll
    for (int j = 0; j < 4; j++) {
        int row = __shfl_sync(FULLM, sgid_r, kb + 8 * j);
        zr[j] = *(const float4*)(zb + (size_t)row * 64 + f4);
    }

    for (int cc = 0; cc < NC; cc++) {
        size_t ci = ci0 + cc;
#pragma unroll
        for (int j = 0; j < 4; j++) {
            int k = kb + 8 * j;
            sA[(f4 + 0) * XS + k] = fmaxf(zr[j].x + dv.x, 0.f);
            sA[(f4 + 1) * XS + k] = fmaxf(zr[j].y + dv.y, 0.f);
            sA[(f4 + 2) * XS + k] = fmaxf(zr[j].z + dv.z, 0.f);
            sA[(f4 + 3) * XS + k] = fmaxf(zr[j].w + dv.w, 0.f);
        }
        if (cc + 1 < NC) {
            size_t cin = ci + 1;
            sgid_r = g_gidx[cin * KS + lane];
            float cx = __ldg(newxyz + cin * 3);
            float cy = __ldg(newxyz + cin * 3 + 1);
            float cz = __ldg(newxyz + cin * 3 + 2);
            dv.x = -(dwx.x * cx + dwy.x * cy + dwz.x * cz);
            dv.y = -(dwx.y * cx + dwy.y * cy + dwz.y * cz);
            dv.z = -(dwx.z * cx + dwy.z * cy + dwz.z * cz);
            dv.w = -(dwx.w * cx + dwy.w * cy + dwz.w * cz);
#pragma unroll
            for (int j = 0; j < 4; j++) {
                int row = __shfl_sync(FULLM, sgid_r, kb + 8 * j);
                zr[j] = *(const float4*)(zb + (size_t)row * 64 + f4);
            }
        }
        __syncthreads();

        layer64(sA, g_w1t, sB, sc + 64, bi + 64, kg, lane);
        __syncwarp();   // sB k-slices warp-local; order STS->LDS within warp
        layer128max(sB, g_w2t, spm, sc + 128, bi + 128, kg, lane);
        __syncthreads();

        float r = fmaxf(fmaxf(spm[t], spm[128 + t]), fmaxf(spm[256 + t], spm[384 + t]));
        outp[ci * 128 + t] = r;
    }
}

// ---------------------------------------------------------------------------
// Single-stream, serial (overlap measured as a loser in R6/R7).
// ---------------------------------------------------------------------------
extern "C" void kernel_launch(void* const* d_in, const int* in_sizes, int n_in,
                              void* d_out, int out_size) {
    const float* xyz = (const float*)d_in[0];
    const float* points = (const float*)d_in[1];
    const float* w0 = (const float*)d_in[2];
    const float* b0 = (const float*)d_in[3];
    const float* g0 = (const float*)d_in[4];
    const float* be0 = (const float*)d_in[5];
    const float* m0 = (const float*)d_in[6];
    const float* v0 = (const float*)d_in[7];
    const float* w1 = (const float*)d_in[8];
    const float* b1 = (const float*)d_in[9];
    const float* g1 = (const float*)d_in[10];
    const float* be1 = (const float*)d_in[11];
    const float* m1 = (const float*)d_in[12];
    const float* v1 = (const float*)d_in[13];
    const float* w2 = (const float*)d_in[14];
    const float* b2 = (const float*)d_in[15];
    const float* g2 = (const float*)d_in[16];
    const float* be2 = (const float*)d_in[17];
    const float* m2 = (const float*)d_in[18];
    const float* v2 = (const float*)d_in[19];

    float* out = (float*)d_out;
    float* newxyz = out;                          // [B, SP, 3]
    float* newpts = out + (size_t)BB * SP * 3;    // [B, SP, 128]

    prep_kernel<<<1, 256>>>(w0, b0, g0, be0, m0, v0,
                            w1, b1, g1, be1, m1, v1,
                            w2, b2, g2, be2, m2, v2);
    zprep_kernel<<<BB * NN / 32, 128>>>(xyz, points);
    fps_kernel<<<BB, 512>>>(newxyz);
    ballquery_kernel<<<BB * SP / 4, 128>>>(newxyz);
    mlp_kernel<<<BB * SP / NC, 128>>>(newxyz, newpts);
}

// round 16
// speedup vs baseline: 1.3685x; 1.0028x over previous
#include <cuda_runtime.h>

#define BB 8
#define NN 4096
#define DD 64
#define SP 1024   // NPOINT
#define KS 32     // NSAMPLE
#define NC 8      // centers per MLP block
#define XS 36     // activation row stride (floats); 16B-aligned rows
#define FULLM 0xffffffffu

__device__ int g_gidx[BB * SP * KS];
__device__ float g_w0t[67 * 64];            // [c][o]
__device__ float g_w1t[64 * 64];            // [c][o]
__device__ float g_w2t[64 * 128];           // [c][o]
__device__ float g_scbi[512];               // sc[256] | bi[256]
__device__ float g_dw[3 * 64];              // sc0[o]*W0[o][c], c<3
__device__ float g_z[BB * NN * 64];         // precomputed layer0 (abs coords), 8MB
__device__ float4 g_xyz4[BB * NN];          // xyz as float4 (w=0), filled by zprep

// ---------------- f32x2 packed helpers (per-half .rn == scalar .rn) --------
__device__ __forceinline__ unsigned long long packf2(float a, float b) {
    unsigned long long r;
    unsigned ua = __float_as_uint(a), ub = __float_as_uint(b);
    asm("mov.b64 %0, {%1, %2};" : "=l"(r) : "r"(ua), "r"(ub));
    return r;
}
__device__ __forceinline__ void unpackf2(unsigned long long v, float& a, float& b) {
    unsigned ua, ub;
    asm("mov.b64 {%0, %1}, %2;" : "=r"(ua), "=r"(ub) : "l"(v));
    a = __uint_as_float(ua); b = __uint_as_float(ub);
}
__device__ __forceinline__ unsigned long long addf2(unsigned long long a, unsigned long long b) {
    unsigned long long r;
    asm("add.rn.f32x2 %0, %1, %2;" : "=l"(r) : "l"(a), "l"(b));
    return r;
}
__device__ __forceinline__ unsigned long long mulf2(unsigned long long a, unsigned long long b) {
    unsigned long long r;
    asm("mul.rn.f32x2 %0, %1, %2;" : "=l"(r) : "l"(a), "l"(b));
    return r;
}
__device__ __forceinline__ void fmaf2(unsigned long long& acc, unsigned long long a,
                                      unsigned long long b) {
    asm("fma.rn.f32x2 %0, %1, %2, %0;" : "+l"(acc) : "l"(a), "l"(b));
}

// ---------------------------------------------------------------------------
// FPS — R14/R10 verbatim (confirmed floor ~313us). One block/batch, 512
// threads x 8 points (4 f32x2 pairs), in-loop argmax interleaved with the
// distance math, REDUX.SYNC, one barrier + parity partials, float4 centroid
// LDG, direct per-iteration newxyz STG.
// Distances (dx^2+dy^2)+dz^2 all .rn == reference; first-index tie-break.
// ---------------------------------------------------------------------------
__global__ __launch_bounds__(512) void fps_kernel(float* __restrict__ newxyz) {
    const int b = blockIdx.x;
    const int tid = threadIdx.x;
    const int lane = tid & 31;
    const int w = tid >> 5;                 // 16 warps
    __shared__ unsigned long long part[2][16];

    const float4* xb4 = g_xyz4 + (size_t)b * NN;
    unsigned long long pxp[4], pyp[4], pzp[4];
    float dist[8];
#pragma unroll
    for (int jp = 0; jp < 4; jp++) {
        float4 f0 = __ldg(xb4 + tid + (2 * jp) * 512);
        float4 f1 = __ldg(xb4 + tid + (2 * jp + 1) * 512);
        pxp[jp] = packf2(f0.x, f1.x);
        pyp[jp] = packf2(f0.y, f1.y);
        pzp[jp] = packf2(f0.z, f1.z);
        dist[2 * jp] = 1e10f;
        dist[2 * jp + 1] = 1e10f;
    }

    int far = 0;
    for (int it = 0; it < SP; it++) {
        const int p = it & 1;
        float4 cen = __ldg(xb4 + far);      // 1 LDG.128 on the critical path
        if (tid == 0) {
            size_t o = ((size_t)b * SP + it) * 3;
            newxyz[o] = cen.x; newxyz[o + 1] = cen.y; newxyz[o + 2] = cen.z;
        }
        unsigned long long ncx = packf2(-cen.x, -cen.x);
        unsigned long long ncy = packf2(-cen.y, -cen.y);
        unsigned long long ncz = packf2(-cen.z, -cen.z);

        float bd = -1.0f;
        int bj = 0;
#pragma unroll
        for (int jp = 0; jp < 4; jp++) {
            unsigned long long dx = addf2(pxp[jp], ncx);   // a-b == a+(-b) exactly
            unsigned long long dy = addf2(pyp[jp], ncy);
            unsigned long long dz = addf2(pzp[jp], ncz);
            unsigned long long s = addf2(mulf2(dx, dx), mulf2(dy, dy));
            s = addf2(s, mulf2(dz, dz));
            float d0, d1;
            unpackf2(s, d0, d1);
            d0 = fminf(dist[2 * jp], d0);
            d1 = fminf(dist[2 * jp + 1], d1);
            dist[2 * jp] = d0;
            dist[2 * jp + 1] = d1;
            if (d0 > bd) { bd = d0; bj = 2 * jp; }       // strict > keeps earliest j
            if (d1 > bd) { bd = d1; bj = 2 * jp + 1; }
        }
        unsigned gidx = (unsigned)(tid + bj * 512);
        unsigned ub = __float_as_uint(bd);               // positive floats monotone as u32
        unsigned m = __reduce_max_sync(FULLM, ub);
        unsigned key = (ub == m) ? gidx : 0x7fffffffu;
        unsigned mi = __reduce_min_sync(FULLM, key);
        if (lane == 0) part[p][w] = ((unsigned long long)m << 32) | mi;
        __syncthreads();
        unsigned long long v = part[p][lane & 15];       // dup lanes harmless for max/min
        unsigned um = (unsigned)(v >> 32);
        unsigned ui = (unsigned)v;
        unsigned m2 = __reduce_max_sync(FULLM, um);
        unsigned key2 = (um == m2) ? ui : 0x7fffffffu;
        far = (int)__reduce_min_sync(FULLM, key2);
        // no second barrier: parity double-buffer
    }
}

// ---------------------------------------------------------------------------
// Ball query — R15 version (measured 25.8us): one warp per center, 128
// points per loop iteration (4 float4 LDGs + 4 ballots). First KS hits in
// ascending index order (prefix chained across the 4 masks).
// ---------------------------------------------------------------------------
__global__ __launch_bounds__(128) void ballquery_kernel(const float* __restrict__ newxyz) {
    int gw = blockIdx.x * 4 + (threadIdx.x >> 5);
    int lane = threadIdx.x & 31;
    int b = gw >> 10;
    int s = gw & 1023;
    const float4* xb4 = g_xyz4 + (size_t)b * NN;
    size_t ci = (size_t)b * SP + s;
    float cx = newxyz[ci * 3], cy = newxyz[ci * 3 + 1], cz = newxyz[ci * 3 + 2];
    int* gp = g_gidx + ci * KS;
    const unsigned lm = (1u << lane) - 1u;

    int count = 0, first = -1;
    for (int base = 0; base < NN; base += 128) {
        unsigned msk[4];
        bool val[4];
#pragma unroll
        for (int q = 0; q < 4; q++) {
            int j = base + 32 * q + lane;
            float4 pt = __ldg(xb4 + j);
            float d = __fadd_rn(
                __fadd_rn(__fmul_rn(__fsub_rn(cx, pt.x), __fsub_rn(cx, pt.x)),
                          __fmul_rn(__fsub_rn(cy, pt.y), __fsub_rn(cy, pt.y))),
                __fmul_rn(__fsub_rn(cz, pt.z), __fsub_rn(cz, pt.z)));
            val[q] = !(d > 0.04f);
            msk[q] = __ballot_sync(FULLM, val[q]);
        }
#pragma unroll
        for (int q = 0; q < 4; q++) {
            if (first < 0 && msk[q]) first = base + 32 * q + __ffs(msk[q]) - 1;
            int pos = count + __popc(msk[q] & lm);
            if (val[q] && pos < KS) gp[pos] = base + 32 * q + lane;
            count += __popc(msk[q]);
        }
        if (count >= KS) break;
    }
    if (lane >= count) gp[lane] = first;
}

// ---------------------------------------------------------------------------
// Prep: fold BN into scale/bias; transpose weights to [c][o]; g_dw.
// ---------------------------------------------------------------------------
__global__ void prep_kernel(
    const float* __restrict__ w0, const float* __restrict__ b0,
    const float* __restrict__ g0, const float* __restrict__ be0,
    const float* __restrict__ m0, const float* __restrict__ v0,
    const float* __restrict__ w1, const float* __restrict__ b1,
    const float* __restrict__ g1, const float* __restrict__ be1,
    const float* __restrict__ m1, const float* __restrict__ v1,
    const float* __restrict__ w2, const float* __restrict__ b2,
    const float* __restrict__ g2, const float* __restrict__ be2,
    const float* __restrict__ m2, const float* __restrict__ v2) {
    int t = threadIdx.x;  // 256
    {
        float g, bb, be, m, v;
        if (t < 64)       { int o = t;       g = g0[o]; bb = b0[o]; be = be0[o]; m = m0[o]; v = v0[o]; }
        else if (t < 128) { int o = t - 64;  g = g1[o]; bb = b1[o]; be = be1[o]; m = m1[o]; v = v1[o]; }
        else              { int o = t - 128; g = g2[o]; bb = b2[o]; be = be2[o]; m = m2[o]; v = v2[o]; }
        float sc = g * rsqrtf(v + 1e-5f);
        g_scbi[t] = sc;
        g_scbi[256 + t] = fmaf(sc, bb - m, be);
    }
    if (t < 192) {  // g_dw[c][o] = sc0[o] * w0[o][c], c<3 (sc recomputed, no bar)
        int c = t >> 6, o = t & 63;
        g_dw[t] = g0[o] * rsqrtf(v0[o] + 1e-5f) * w0[o * 67 + c];
    }
    for (int i = t; i < 64 * 67; i += 256) { int o = i / 67, c = i - o * 67; g_w0t[c * 64 + o] = w0[i]; }
    for (int i = t; i < 64 * 64; i += 256) { int o = i >> 6, c = i & 63; g_w1t[c * 64 + o] = w1[i]; }
    for (int i = t; i < 128 * 64; i += 256) { int o = i >> 6, c = i & 63; g_w2t[c * 128 + o] = w2[i]; }
}

// ---------------------------------------------------------------------------
// Z precompute: Z[j][o] = sc0[o]*(W0 @ [xyz_j; pts_j])[o] + bi0[o]  (no relu).
// Also fills this block's 32 g_xyz4 entries (folds the old xyz4_kernel).
// ---------------------------------------------------------------------------
__global__ __launch_bounds__(128) void zprep_kernel(const float* __restrict__ xyz,
                                                    const float* __restrict__ points) {
    __shared__ __align__(16) float sF[67 * XS];
    __shared__ __align__(16) float sB[32 * 64];   // [k][o] for coalesced STG
    int t = threadIdx.x;
    int lane = t & 31, kg = t >> 5;
    int b = blockIdx.x >> 7;
    int j0 = (blockIdx.x & 127) * 32;
    const size_t rowb = (size_t)b * NN + j0;

    if (t < 96) { int c = t / 32, k = t % 32; sF[c * XS + k] = xyz[(rowb + k) * 3 + c]; }
    for (int i = t; i < 32 * 64; i += 128) {
        int c = i & 63, k = i >> 6;
        sF[(3 + c) * XS + k] = points[(rowb + k) * DD + c];
    }
    if (t < 32) {   // fold xyz4: one float4 store per point (coalesced)
        int k = t;
        g_xyz4[rowb + k] = make_float4(xyz[(rowb + k) * 3],
                                       xyz[(rowb + k) * 3 + 1],
                                       xyz[(rowb + k) * 3 + 2], 0.f);
    }
    __syncthreads();

    unsigned long long acc[2][4];
#pragma unroll
    for (int i = 0; i < 2; i++)
#pragma unroll
        for (int jp = 0; jp < 4; jp++) acc[i][jp] = 0ull;
    const float* xbase = sF + kg * 8;
#pragma unroll 4
    for (int c = 0; c < 67; c++) {
        ulonglong2 xv01 = *(const ulonglong2*)(xbase + c * XS);
        ulonglong2 xv23 = *(const ulonglong2*)(xbase + c * XS + 4);
        float2 wv = *(const float2*)(g_w0t + c * 64 + 2 * lane);
        unsigned long long w0p = packf2(wv.x, wv.x);
        unsigned long long w1p = packf2(wv.y, wv.y);
        fmaf2(acc[0][0], xv01.x, w0p); fmaf2(acc[0][1], xv01.y, w0p);
        fmaf2(acc[0][2], xv23.x, w0p); fmaf2(acc[0][3], xv23.y, w0p);
        fmaf2(acc[1][0], xv01.x, w1p); fmaf2(acc[1][1], xv01.y, w1p);
        fmaf2(acc[1][2], xv23.x, w1p); fmaf2(acc[1][3], xv23.y, w1p);
    }
    {
        int o = 2 * lane;
        float s0 = g_scbi[o], b0_ = g_scbi[256 + o];
        float s1 = g_scbi[o + 1], b1_ = g_scbi[256 + o + 1];
#pragma unroll
        for (int jp = 0; jp < 4; jp++) {
            float a0, a1, c0, c1;
            unpackf2(acc[0][jp], a0, a1);
            unpackf2(acc[1][jp], c0, c1);
            int k = kg * 8 + 2 * jp;
            *(float2*)(sB + k * 64 + o) = make_float2(fmaf(a0, s0, b0_), fmaf(c0, s1, b1_));
            *(float2*)(sB + (k + 1) * 64 + o) = make_float2(fmaf(a1, s0, b0_), fmaf(c1, s1, b1_));
        }
    }
    __syncthreads();
    for (int i = t; i < 32 * 64; i += 128) {
        int o = i & 63, k = i >> 6;
        g_z[(rowb + k) * 64 + o] = sB[k * 64 + o];
    }
}

// ---------------------------------------------------------------------------
// MLP layers l1/l2 — R10 verbatim (scalar-weight loads + in-register pack).
// Activations [c][k] stride XS; warp kg owns k kg*8..+7.
// ---------------------------------------------------------------------------
__device__ __forceinline__ void layer64(const float* __restrict__ X,
                                        const float* __restrict__ Wg,
                                        float* __restrict__ Y,
                                        const float* __restrict__ scp,
                                        const float* __restrict__ bip,
                                        int kg, int lane) {
    unsigned long long acc[2][4];
#pragma unroll
    for (int i = 0; i < 2; i++)
#pragma unroll
        for (int jp = 0; jp < 4; jp++) acc[i][jp] = 0ull;
    const float* xbase = X + kg * 8;
#pragma unroll 4
    for (int c = 0; c < 64; c++) {
        ulonglong2 xv01 = *(const ulonglong2*)(xbase + c * XS);
        ulonglong2 xv23 = *(const ulonglong2*)(xbase + c * XS + 4);
        float2 wv = *(const float2*)(Wg + c * 64 + 2 * lane);
        unsigned long long w0p = packf2(wv.x, wv.x);
        unsigned long long w1p = packf2(wv.y, wv.y);
        fmaf2(acc[0][0], xv01.x, w0p); fmaf2(acc[0][1], xv01.y, w0p);
        fmaf2(acc[0][2], xv23.x, w0p); fmaf2(acc[0][3], xv23.y, w0p);
        fmaf2(acc[1][0], xv01.x, w1p); fmaf2(acc[1][1], xv01.y, w1p);
        fmaf2(acc[1][2], xv23.x, w1p); fmaf2(acc[1][3], xv23.y, w1p);
    }
#pragma unroll
    for (int i = 0; i < 2; i++) {
        int o = 2 * lane + i;
        float s = scp[o], bb = bip[o];
        float* yr = Y + o * XS + kg * 8;
#pragma unroll
        for (int jp = 0; jp < 4; jp++) {
            float v0, v1;
            unpackf2(acc[i][jp], v0, v1);
            yr[2 * jp] = fmaxf(fmaf(v0, s, bb), 0.f);
            yr[2 * jp + 1] = fmaxf(fmaf(v1, s, bb), 0.f);
        }
    }
}

__device__ __forceinline__ void layer128max(const float* __restrict__ X,
                                            const float* __restrict__ Wg,
                                            float* __restrict__ spm,
                                            const float* __restrict__ scp,
                                            const float* __restrict__ bip,
                                            int kg, int lane) {
    unsigned long long acc[4][4];
#pragma unroll
    for (int i = 0; i < 4; i++)
#pragma unroll
        for (int jp = 0; jp < 4; jp++) acc[i][jp] = 0ull;
    const float* xbase = X + kg * 8;
#pragma unroll 2
    for (int c = 0; c < 64; c++) {
        ulonglong2 xv01 = *(const ulonglong2*)(xbase + c * XS);
        ulonglong2 xv23 = *(const ulonglong2*)(xbase + c * XS + 4);
        float4 wv = *(const float4*)(Wg + c * 128 + 4 * lane);
        unsigned long long wp0 = packf2(wv.x, wv.x);
        unsigned long long wp1 = packf2(wv.y, wv.y);
        unsigned long long wp2 = packf2(wv.z, wv.z);
        unsigned long long wp3 = packf2(wv.w, wv.w);
        fmaf2(acc[0][0], xv01.x, wp0); fmaf2(acc[0][1], xv01.y, wp0);
        fmaf2(acc[0][2], xv23.x, wp0); fmaf2(acc[0][3], xv23.y, wp0);
        fmaf2(acc[1][0], xv01.x, wp1); fmaf2(acc[1][1], xv01.y, wp1);
        fmaf2(acc[1][2], xv23.x, wp1); fmaf2(acc[1][3], xv23.y, wp1);
        fmaf2(acc[2][0], xv01.x, wp2); fmaf2(acc[2][1], xv01.y, wp2);
        fmaf2(acc[2][2], xv23.x, wp2); fmaf2(acc[2][3], xv23.y, wp2);
        fmaf2(acc[3][0], xv01.x, wp3); fmaf2(acc[3][1], xv01.y, wp3);
        fmaf2(acc[3][2], xv23.x, wp3); fmaf2(acc[3][3], xv23.y, wp3);
    }
#pragma unroll
    for (int i = 0; i < 4; i++) {
        int o = 4 * lane + i;
        float s = scp[o], bb = bip[o];
        float mx = 0.f;  // relu >= 0
#pragma unroll
        for (int jp = 0; jp < 4; jp++) {
            float v0, v1;
            unpackf2(acc[i][jp], v0, v1);
            mx = fmaxf(mx, fmaf(v0, s, bb));
            mx = fmaxf(mx, fmaf(v1, s, bb));
        }
        spm[kg * 128 + o] = mx;
    }
}

// ---------------------------------------------------------------------------
// MLP: gather pipelined one center ahead; sgid in registers + shfl; dvec
// per-thread from hoisted g_dw registers. 2 barriers per center. (R10/R14)
// ---------------------------------------------------------------------------
__global__ __launch_bounds__(128) void mlp_kernel(const float* __restrict__ newxyz,
                                                  float* __restrict__ outp) {
    __shared__ __align__(16) float sA[64 * XS];
    __shared__ __align__(16) float sB[64 * XS];
    __shared__ float spm[512];

    int t = threadIdx.x;
    int lane = t & 31, kg = t >> 5;
    int b = blockIdx.x >> 7;
    int sbase = (blockIdx.x & 127) * NC;
    const float* sc = g_scbi;
    const float* bi = g_scbi + 256;
    const float* zb = g_z + (size_t)b * NN * 64;
    const int f4 = (t & 15) * 4;          // base channel for this thread
    const int kb = t >> 4;                // base k (0..7)

    const float4 dwx = *(const float4*)(g_dw + f4);
    const float4 dwy = *(const float4*)(g_dw + 64 + f4);
    const float4 dwz = *(const float4*)(g_dw + 128 + f4);

    size_t ci0 = (size_t)b * SP + sbase;

    int sgid_r = g_gidx[ci0 * KS + lane];
    float4 dv;
    {
        float cx = __ldg(newxyz + ci0 * 3);
        float cy = __ldg(newxyz + ci0 * 3 + 1);
        float cz = __ldg(newxyz + ci0 * 3 + 2);
        dv.x = -(dwx.x * cx + dwy.x * cy + dwz.x * cz);
        dv.y = -(dwx.y * cx + dwy.y * cy + dwz.y * cz);
        dv.z = -(dwx.z * cx + dwy.z * cy + dwz.z * cz);
        dv.w = -(dwx.w * cx + dwy.w * cy + dwz.w * cz);
    }
    float4 zr[4];
#pragma unroll
    for (int j = 0; j < 4; j++) {
        int row = __shfl_sync(FULLM, sgid_r, kb + 8 * j);
        zr[j] = *(const float4*)(zb + (size_t)row * 64 + f4);
    }

    for (int cc = 0; cc < NC; cc++) {
        size_t ci = ci0 + cc;
#pragma unroll
        for (int j = 0; j < 4; j++) {
            int k = kb + 8 * j;
            sA[(f4 + 0) * XS + k] = fmaxf(zr[j].x + dv.x, 0.f);
            sA[(f4 + 1) * XS + k] = fmaxf(zr[j].y + dv.y, 0.f);
            sA[(f4 + 2) * XS + k] = fmaxf(zr[j].z + dv.z, 0.f);
            sA[(f4 + 3) * XS + k] = fmaxf(zr[j].w + dv.w, 0.f);
        }
        if (cc + 1 < NC) {
            size_t cin = ci + 1;
            sgid_r = g_gidx[cin * KS + lane];
            float cx = __ldg(newxyz + cin * 3);
            float cy = __ldg(newxyz + cin * 3 + 1);
            float cz = __ldg(newxyz + cin * 3 + 2);
            dv.x = -(dwx.x * cx + dwy.x * cy + dwz.x * cz);
            dv.y = -(dwx.y * cx + dwy.y * cy + dwz.y * cz);
            dv.z = -(dwx.z * cx + dwy.z * cy + dwz.z * cz);
            dv.w = -(dwx.w * cx + dwy.w * cy + dwz.w * cz);
#pragma unroll
            for (int j = 0; j < 4; j++) {
                int row = __shfl_sync(FULLM, sgid_r, kb + 8 * j);
                zr[j] = *(const float4*)(zb + (size_t)row * 64 + f4);
            }
        }
        __syncthreads();

        layer64(sA, g_w1t, sB, sc + 64, bi + 64, kg, lane);
        __syncwarp();   // sB k-slices warp-local; order STS->LDS within warp
        layer128max(sB, g_w2t, spm, sc + 128, bi + 128, kg, lane);
        __syncthreads();

        float r = fmaxf(fmaxf(spm[t], spm[128 + t]), fmaxf(spm[256 + t], spm[384 + t]));
        outp[ci * 128 + t] = r;
    }
}

// ---------------------------------------------------------------------------
// Single-stream, serial (overlap measured as a loser in R6/R7).
// ---------------------------------------------------------------------------
extern "C" void kernel_launch(void* const* d_in, const int* in_sizes, int n_in,
                              void* d_out, int out_size) {
    const float* xyz = (const float*)d_in[0];
    const float* points = (const float*)d_in[1];
    const float* w0 = (const float*)d_in[2];
    const float* b0 = (const float*)d_in[3];
    const float* g0 = (const float*)d_in[4];
    const float* be0 = (const float*)d_in[5];
    const float* m0 = (const float*)d_in[6];
    const float* v0 = (const float*)d_in[7];
    const float* w1 = (const float*)d_in[8];
    const float* b1 = (const float*)d_in[9];
    const float* g1 = (const float*)d_in[10];
    const float* be1 = (const float*)d_in[11];
    const float* m1 = (const float*)d_in[12];
    const float* v1 = (const float*)d_in[13];
    const float* w2 = (const float*)d_in[14];
    const float* b2 = (const float*)d_in[15];
    const float* g2 = (const float*)d_in[16];
    const float* be2 = (const float*)d_in[17];
    const float* m2 = (const float*)d_in[18];
    const float* v2 = (const float*)d_in[19];

    float* out = (float*)d_out;
    float* newxyz = out;                          // [B, SP, 3]
    float* newpts = out + (size_t)BB * SP * 3;    // [B, SP, 128]

    prep_kernel<<<1, 256>>>(w0, b0, g0, be0, m0, v0,
                            w1, b1, g1, be1, m1, v1,
                            w2, b2, g2, be2, m2, v2);
    zprep_kernel<<<BB * NN / 32, 128>>>(xyz, points);
    fps_kernel<<<BB, 512>>>(newxyz);
    ballquery_kernel<<<BB * SP / 4, 128>>>(newxyz);
    mlp_kernel<<<BB * SP / NC, 128>>>(newxyz, newpts);
}